// round 15
// baseline (speedup 1.0000x reference)
#include <cuda_runtime.h>
#include <cuda_bf16.h>
#include <cuda_fp16.h>
#include <cuda_fp8.h>
#include <cstdint>
#include <cstddef>

// ---------------- problem constants ----------------
#define INDIM  1024
#define OUTDIM 2048
#define BATCH  8192

#define BM 128
#define BN 128
#define BK 128                   // fp8 elems per stage = 128 B row (swizzle atom)
#define NSTAGE_K (INDIM / BK)    // 8
#define STAGES 3
#define GEMM_THREADS 256

// P is scaled by 32 before fp8 quantization; epilogue multiplies acc by 2/32.
#define ACC_SCALE 0.0625f

#define SMEM_PSQ_OFF   0u
#define SMEM_TILES_OFF 1024u
#define STAGE_BYTES    ((BM + BN) * 128u)                       // 32768
#define SMEM_TOTAL     (SMEM_TILES_OFF + STAGES * STAGE_BYTES)  // 99328 (x2 CTAs = 194KB/SM)

// fused grid layout
#define CONV_BLOCKS  (BATCH / 8)          // 1024 blocks, 8 rows each (warp-per-row)
#define TR_NBLK      (OUTDIM / 32)        // 64 n-blocks of 32
#define TR_KBLK      (INDIM / 128)        // 8 k-blocks of 128
#define TR_BLOCKS    (TR_NBLK * TR_KBLK)  // 512
#define PREP_BLOCKS  (CONV_BLOCKS + TR_BLOCKS)   // 1536
#define GEMM_BLOCKS  ((OUTDIM / BN) * (BATCH / BM))             // 1024
#define TOTAL_BLOCKS (PREP_BLOCKS + GEMM_BLOCKS)                // 2560
#define N_MTILE      (BATCH / BM)         // 64
#define N_NTILE      (OUTDIM / BN)        // 16

// ---------------- device scratch (alloc-free) ----------------
__device__ __align__(128) uint8_t g_x_fp8[(size_t)BATCH * INDIM];   // 8 MB, e4m3
__device__ __align__(128) uint8_t g_pt_fp8[(size_t)OUTDIM * INDIM]; // 2 MB, [n][k], e4m3 of 32*p
__device__ float g_x_sq[BATCH];
__device__ float g_psq_part[TR_KBLK][OUTDIM];   // 64 KB partial column norms
// producer->consumer flags (zero-initialized; self-reset at end of each run)
__device__ int g_conv_ctr[N_MTILE];   // 16 conv blocks per m-tile
__device__ int g_tr_ctr[N_NTILE];     // 32 tr blocks per n-tile
__device__ int g_done;

// ---------------- helpers ----------------
__device__ __forceinline__ uint32_t smem_to_u32(const void* p) {
    uint32_t a;
    asm("{ .reg .u64 t; cvta.to.shared.u64 t, %1; cvt.u32.u64 %0, t; }" : "=r"(a) : "l"(p));
    return a;
}
__device__ __forceinline__ uint32_t sw128(uint32_t off) {
    return off ^ ((off >> 3) & 0x70);
}
__device__ __forceinline__ void cp_async16(uint32_t dst, const void* src) {
    asm volatile("cp.async.cg.shared.global [%0], [%1], 16;" :: "r"(dst), "l"(src) : "memory");
}
#define CP_COMMIT() asm volatile("cp.async.commit_group;" ::: "memory")
#define CP_WAIT(n)  asm volatile("cp.async.wait_group %0;" :: "n"(n) : "memory")

__device__ __forceinline__ void ldmatrix_x4(uint32_t* r, uint32_t addr) {
    asm volatile("ldmatrix.sync.aligned.m8n8.x4.shared.b16 {%0,%1,%2,%3}, [%4];"
                 : "=r"(r[0]), "=r"(r[1]), "=r"(r[2]), "=r"(r[3]) : "r"(addr));
}
// fp8 e4m3 MMA with fp16 accumulator (2 packed f16x2 regs).
__device__ __forceinline__ void mma_fp8_h(uint32_t* c, const uint32_t* a, const uint32_t* b) {
    asm volatile(
        "mma.sync.aligned.m16n8k32.row.col.f16.e4m3.e4m3.f16 "
        "{%0,%1}, {%2,%3,%4,%5}, {%6,%7}, {%0,%1};"
        : "+r"(c[0]), "+r"(c[1])
        : "r"(a[0]), "r"(a[1]), "r"(a[2]), "r"(a[3]), "r"(b[0]), "r"(b[1]));
}

__device__ __forceinline__ uint8_t to_e4m3(float v) {
    return (uint8_t)__nv_cvt_float_to_fp8(v, __NV_SATFINITE, __NV_E4M3);
}

// ---------------- fused everything kernel ----------------
// blocks [0, CONV_BLOCKS): convert x -> fp8 + row norms; signal g_conv_ctr.
// blocks [CONV_BLOCKS, PREP_BLOCKS): transpose+quantize P; signal g_tr_ctr.
// blocks [PREP_BLOCKS, TOTAL_BLOCKS): GEMM tiles; spin on their producers' flags.
__global__ void __launch_bounds__(GEMM_THREADS, 2)
fused_kernel(const float* __restrict__ x, const float* __restrict__ p,
             float* __restrict__ out) {
    extern __shared__ char smem[];
    const int tid = threadIdx.x;
    const int bid = blockIdx.x;

    if (bid < CONV_BLOCKS) {
        // ---- x convert: warp-per-row ----
        const int warp = tid >> 5, lane = tid & 31;
        const int row = bid * 8 + warp;
        const float4* xr = reinterpret_cast<const float4*>(x + (size_t)row * INDIM);
        uchar4* dst = reinterpret_cast<uchar4*>(g_x_fp8 + (size_t)row * INDIM);
        float acc = 0.f;
        float4 v[8];
#pragma unroll
        for (int j = 0; j < 8; j++) v[j] = xr[lane + 32 * j];
#pragma unroll
        for (int j = 0; j < 8; j++) {
            acc += v[j].x * v[j].x + v[j].y * v[j].y + v[j].z * v[j].z + v[j].w * v[j].w;
            uchar4 q;
            q.x = to_e4m3(v[j].x); q.y = to_e4m3(v[j].y);
            q.z = to_e4m3(v[j].z); q.w = to_e4m3(v[j].w);
            dst[lane + 32 * j] = q;
        }
#pragma unroll
        for (int o = 16; o > 0; o >>= 1) acc += __shfl_xor_sync(0xFFFFFFFFu, acc, o);
        if (lane == 0) g_x_sq[row] = acc;
        __syncthreads();
        __threadfence();
        if (tid == 0) atomicAdd(&g_conv_ctr[bid >> 4], 1);   // 16 blocks per m-tile
        return;
    }

    if (bid < PREP_BLOCKS) {
        // ---- P transpose/quantize: 32n x 128k tile, 16B vector stores ----
        float (*tile)[33] = reinterpret_cast<float(*)[33]>(smem);               // [128][33]
        float (*partial)[33] = reinterpret_cast<float(*)[33]>(smem + 128 * 33 * 4);  // [8][33]
        const int b2 = bid - CONV_BLOCKS;
        const int n0 = (b2 % TR_NBLK) * 32;
        const int k_blk = b2 / TR_NBLK;     // 0..7
        const int k0 = k_blk * 128;
        const int lane = tid & 31, w = tid >> 5;
#pragma unroll
        for (int kk = 0; kk < 128; kk += 8)
            tile[kk + w][lane] = p[(size_t)(k0 + kk + w) * OUTDIM + n0 + lane];
        __syncthreads();
        {
            union { uint4 u; uint8_t b[16]; } pk;
            float sq = 0.f;
#pragma unroll
            for (int j = 0; j < 16; j++) {
                float v = tile[w * 16 + j][lane];
                sq += v * v;
                pk.b[j] = to_e4m3(32.0f * v);
            }
            *reinterpret_cast<uint4*>(g_pt_fp8 + (size_t)(n0 + lane) * INDIM + k0 + w * 16) = pk.u;
            partial[w][lane] = sq;
        }
        __syncthreads();
        if (w == 0) {
            float s = 0.f;
#pragma unroll
            for (int j = 0; j < 8; j++) s += partial[j][lane];
            g_psq_part[k_blk][n0 + lane] = s;
        }
        __syncthreads();
        __threadfence();
        if (tid == 0) atomicAdd(&g_tr_ctr[(b2 % TR_NBLK) >> 2], 1);   // 32 blocks per n-tile
        return;
    }

    // ------------------- GEMM part (R14 champion config) -------------------
    uint32_t smem_base = smem_to_u32(smem);
    const int g = bid - PREP_BLOCKS;
    const int bx = g & (N_NTILE - 1);
    const int by = g >> 4;
    const int wid = tid >> 5;
    const int lid = tid & 31;
    const int wm = wid & 3;         // 4 warps along M (32 rows each)
    const int wn = wid >> 2;        // 2 warps along N (64 cols each)
    const int n0 = bx * BN;
    const int m0 = by * BM;

    // wait for producers of this tile
    if (tid == 0) {
        while (atomicAdd(&g_conv_ctr[by], 0) < 16) { }
        while (atomicAdd(&g_tr_ctr[bx], 0) < 32) { }
    }
    __syncthreads();
    __threadfence();

    // prologue loads first so the psq reduction below overlaps the cp.async latency
#pragma unroll
    for (int s = 0; s < STAGES - 1; s++) {
        {
            uint32_t a_s = smem_base + SMEM_TILES_OFF + (uint32_t)s * STAGE_BYTES;
            uint32_t b_s = a_s + BM * 128u;
            const uint8_t* abase = g_x_fp8 + (size_t)m0 * INDIM + s * BK;
#pragma unroll
            for (int i = 0; i < 4; i++) {
                int idx = tid + i * GEMM_THREADS;
                int r = idx >> 3, c = idx & 7;
                cp_async16(a_s + sw128((uint32_t)(r * 128 + c * 16)),
                           abase + (size_t)r * INDIM + c * 16);
            }
            const uint8_t* bbase = g_pt_fp8 + (size_t)n0 * INDIM + s * BK;
#pragma unroll
            for (int i = 0; i < 4; i++) {
                int idx = tid + i * GEMM_THREADS;
                int r = idx >> 3, c = idx & 7;
                cp_async16(b_s + sw128((uint32_t)(r * 128 + c * 16)),
                           bbase + (size_t)r * INDIM + c * 16);
            }
        }
        CP_COMMIT();
    }

    // reduce psq partials into smem tile: psq[n] = sum_k g_psq_part[k][n]
    for (int i = tid; i < BN; i += GEMM_THREADS) {
        float s0 = 0.f, s1 = 0.f, s2 = 0.f, s3 = 0.f;
#pragma unroll
        for (int j = 0; j < TR_KBLK; j += 4) {
            s0 += g_psq_part[j + 0][n0 + i];
            s1 += g_psq_part[j + 1][n0 + i];
            s2 += g_psq_part[j + 2][n0 + i];
            s3 += g_psq_part[j + 3][n0 + i];
        }
        *reinterpret_cast<float*>(smem + SMEM_PSQ_OFF + i * 4) = (s0 + s1) + (s2 + s3);
    }

    uint32_t acc[2][8][2];          // fp16x2 accumulators
#pragma unroll
    for (int mi = 0; mi < 2; mi++)
#pragma unroll
        for (int nt = 0; nt < 8; nt++) {
            acc[mi][nt][0] = 0u; acc[mi][nt][1] = 0u;
        }

    // per-lane ldmatrix row/offset components
    const int a_row = wm * 32 + (lid & 15);                   // + mi*16
    const int a_kb  = (lid >> 4) * 16;
    const int sub   = lid >> 3;
    const int b_row = wn * 64 + (sub >> 1) * 8 + (lid & 7);   // + nj*16
    const int b_kb  = (sub & 1) * 16;

    int buf = 0;
    int pbuf = STAGES - 1;          // buffer to prefetch into
    for (int s = 0; s < NSTAGE_K; s++) {
        CP_WAIT(STAGES - 2);                   // stage s landed (this thread)
        __syncthreads();                       // landed for all; all finished compute(s-1)
        if (s + STAGES - 1 < NSTAGE_K) {
            uint32_t a_s = smem_base + SMEM_TILES_OFF + (uint32_t)pbuf * STAGE_BYTES;
            uint32_t b_s = a_s + BM * 128u;
            const uint8_t* abase = g_x_fp8 + (size_t)m0 * INDIM + (s + STAGES - 1) * BK;
#pragma unroll
            for (int i = 0; i < 4; i++) {
                int idx = tid + i * GEMM_THREADS;
                int r = idx >> 3, c = idx & 7;
                cp_async16(a_s + sw128((uint32_t)(r * 128 + c * 16)),
                           abase + (size_t)r * INDIM + c * 16);
            }
            const uint8_t* bbase = g_pt_fp8 + (size_t)n0 * INDIM + (s + STAGES - 1) * BK;
#pragma unroll
            for (int i = 0; i < 4; i++) {
                int idx = tid + i * GEMM_THREADS;
                int r = idx >> 3, c = idx & 7;
                cp_async16(b_s + sw128((uint32_t)(r * 128 + c * 16)),
                           bbase + (size_t)r * INDIM + c * 16);
            }
        }
        CP_COMMIT();                           // empty group when no loads

        const uint32_t t_s = smem_base + SMEM_TILES_OFF + (uint32_t)buf * STAGE_BYTES;
        const uint32_t a_s = t_s;
        const uint32_t b_s = t_s + BM * 128u;

#pragma unroll
        for (int ks = 0; ks < 4; ks++) {       // 4 k-chunks of 32 bytes
            const int k0b = ks * 32;
            uint32_t afrag[2][4];
#pragma unroll
            for (int mi = 0; mi < 2; mi++) {
                uint32_t off = (uint32_t)((a_row + mi * 16) * 128 + k0b + a_kb);
                ldmatrix_x4(afrag[mi], a_s + sw128(off));
            }
            uint32_t bfrag[8][2];
#pragma unroll
            for (int nj = 0; nj < 4; nj++) {
                uint32_t off = (uint32_t)((b_row + nj * 16) * 128 + k0b + b_kb);
                uint32_t t[4];
                ldmatrix_x4(t, b_s + sw128(off));
                bfrag[nj * 2][0] = t[0]; bfrag[nj * 2][1] = t[1];
                bfrag[nj * 2 + 1][0] = t[2]; bfrag[nj * 2 + 1][1] = t[3];
            }
#pragma unroll
            for (int mi = 0; mi < 2; mi++)
#pragma unroll
                for (int nt = 0; nt < 8; nt++)
                    mma_fp8_h(acc[mi][nt], afrag[mi], bfrag[nt]);
        }
        buf = (buf + 1 == STAGES) ? 0 : buf + 1;
        pbuf = (pbuf + 1 == STAGES) ? 0 : pbuf + 1;
    }

    // fused epilogue: out = (2/32)*acc - x_sq[m] - p_sq[n]
    const float* psq_s = reinterpret_cast<const float*>(smem + SMEM_PSQ_OFF);
    const int lane4 = lid >> 2;
    const int lane2 = (lid & 3) * 2;
#pragma unroll
    for (int mi = 0; mi < 2; mi++) {
#pragma unroll
        for (int h = 0; h < 2; h++) {
            const int r = m0 + wm * 32 + mi * 16 + lane4 + h * 8;
            const float xs = g_x_sq[r];
            float* orow = out + (size_t)r * OUTDIM + n0 + wn * 64;
#pragma unroll
            for (int nt = 0; nt < 8; nt++) {
                const int cn = nt * 8 + lane2;
                __half2 hv = *reinterpret_cast<const __half2*>(&acc[mi][nt][h]);
                float2 w;
                w.x = fmaf(ACC_SCALE, __half2float(__low2half(hv)),
                           -xs - psq_s[wn * 64 + cn]);
                w.y = fmaf(ACC_SCALE, __half2float(__high2half(hv)),
                           -xs - psq_s[wn * 64 + cn + 1]);
                *reinterpret_cast<float2*>(orow + cn) = w;
            }
        }
    }

    // last GEMM block resets all flags so the next graph replay starts clean
    __syncthreads();
    if (tid == 0) {
        int d = atomicAdd(&g_done, 1);
        if (d == GEMM_BLOCKS - 1) {
#pragma unroll
            for (int i = 0; i < N_MTILE; i++) g_conv_ctr[i] = 0;
#pragma unroll
            for (int i = 0; i < N_NTILE; i++) g_tr_ctr[i] = 0;
            g_done = 0;
            __threadfence();
        }
    }
}

// ---------------- launch ----------------
extern "C" void kernel_launch(void* const* d_in, const int* in_sizes, int n_in,
                              void* d_out, int out_size) {
    const float* x = (const float*)d_in[0];
    const float* p = (const float*)d_in[1];
    if (n_in >= 2 && in_sizes[0] == OUTDIM * INDIM && in_sizes[1] == BATCH * INDIM) {
        x = (const float*)d_in[1];
        p = (const float*)d_in[0];
    }
    float* out = (float*)d_out;

    cudaFuncSetAttribute(fused_kernel, cudaFuncAttributeMaxDynamicSharedMemorySize,
                         SMEM_TOTAL);
    fused_kernel<<<TOTAL_BLOCKS, GEMM_THREADS, SMEM_TOTAL>>>(x, p, out);
}

// round 16
// speedup vs baseline: 1.0791x; 1.0791x over previous
#include <cuda_runtime.h>
#include <cuda_bf16.h>
#include <cuda_fp16.h>
#include <cuda_fp8.h>
#include <cstdint>
#include <cstddef>

// ---------------- problem constants ----------------
#define INDIM  1024
#define OUTDIM 2048
#define BATCH  8192

#define BM 128
#define BN 128
#define BK 128                   // fp8 elems per stage = 128 B row (swizzle atom)
#define NSTAGE_K (INDIM / BK)    // 8
#define STAGES 3
#define GEMM_THREADS 256

// P is scaled by 32 before fp8 quantization; epilogue multiplies acc by 2/32.
#define ACC_SCALE 0.0625f

#define SMEM_PSQ_OFF   0u
#define SMEM_TILES_OFF 1024u
#define STAGE_BYTES    ((BM + BN) * 128u)                       // 32768
#define SMEM_TOTAL     (SMEM_TILES_OFF + STAGES * STAGE_BYTES)  // 99328 (x2 CTAs = 194KB/SM)

// prep grid split
#define CONV_BLOCKS  (BATCH / 16)         // 512 blocks, 16 rows each (warp handles 2 rows)
#define TR_NBLK      (OUTDIM / 32)        // 64 n-blocks of 32
#define TR_KBLK      (INDIM / 128)        // 8 k-blocks of 128
#define TR_BLOCKS    (TR_NBLK * TR_KBLK)  // 512
#define PREP_BLOCKS  (CONV_BLOCKS + TR_BLOCKS)   // 1024

// ---------------- device scratch (alloc-free) ----------------
__device__ __align__(128) uint8_t g_x_fp8[(size_t)BATCH * INDIM];   // 8 MB, e4m3
__device__ __align__(128) uint8_t g_pt_fp8[(size_t)OUTDIM * INDIM]; // 2 MB, [n][k], e4m3 of 32*p
__device__ float g_x_sq[BATCH];
__device__ float g_psq_part[TR_KBLK][OUTDIM];   // 64 KB partial column norms

// ---------------- helpers ----------------
__device__ __forceinline__ uint32_t smem_to_u32(const void* p) {
    uint32_t a;
    asm("{ .reg .u64 t; cvta.to.shared.u64 t, %1; cvt.u32.u64 %0, t; }" : "=r"(a) : "l"(p));
    return a;
}
__device__ __forceinline__ uint32_t sw128(uint32_t off) {
    return off ^ ((off >> 3) & 0x70);
}
__device__ __forceinline__ void cp_async16(uint32_t dst, const void* src) {
    asm volatile("cp.async.cg.shared.global [%0], [%1], 16;" :: "r"(dst), "l"(src) : "memory");
}
#define CP_COMMIT() asm volatile("cp.async.commit_group;" ::: "memory")
#define CP_WAIT(n)  asm volatile("cp.async.wait_group %0;" :: "n"(n) : "memory")

__device__ __forceinline__ void ldmatrix_x4(uint32_t* r, uint32_t addr) {
    asm volatile("ldmatrix.sync.aligned.m8n8.x4.shared.b16 {%0,%1,%2,%3}, [%4];"
                 : "=r"(r[0]), "=r"(r[1]), "=r"(r[2]), "=r"(r[3]) : "r"(addr));
}
// fp8 e4m3 MMA with fp16 accumulator (2 packed f16x2 regs).
__device__ __forceinline__ void mma_fp8_h(uint32_t* c, const uint32_t* a, const uint32_t* b) {
    asm volatile(
        "mma.sync.aligned.m16n8k32.row.col.f16.e4m3.e4m3.f16 "
        "{%0,%1}, {%2,%3,%4,%5}, {%6,%7}, {%0,%1};"
        : "+r"(c[0]), "+r"(c[1])
        : "r"(a[0]), "r"(a[1]), "r"(a[2]), "r"(a[3]), "r"(b[0]), "r"(b[1]));
}

__device__ __forceinline__ uint8_t to_e4m3(float v) {
    return (uint8_t)__nv_cvt_float_to_fp8(v, __NV_SATFINITE, __NV_E4M3);
}

// ---------------- fused prep kernel ----------------
// blocks [0, CONV_BLOCKS): convert x -> fp8 + row norms (warp per 2 rows, interleaved).
// blocks [CONV_BLOCKS, PREP_BLOCKS): transpose+quantize P in 32n x 128k tiles
//   with 16B vectorized fp8 stores; write psq partials (8 per column).
__global__ void prep_kernel(const float* __restrict__ x, const float* __restrict__ p) {
    const int tid = threadIdx.x;
    if ((int)blockIdx.x < CONV_BLOCKS) {
        const int warp = tid >> 5, lane = tid & 31;
        const int row0 = blockIdx.x * 16 + warp * 2;
        const float4* xr0 = reinterpret_cast<const float4*>(x + (size_t)row0 * INDIM);
        const float4* xr1 = reinterpret_cast<const float4*>(x + (size_t)(row0 + 1) * INDIM);
        uchar4* dst0 = reinterpret_cast<uchar4*>(g_x_fp8 + (size_t)row0 * INDIM);
        uchar4* dst1 = reinterpret_cast<uchar4*>(g_x_fp8 + (size_t)(row0 + 1) * INDIM);
        float4 v0[8], v1[8];
#pragma unroll
        for (int j = 0; j < 8; j++) { v0[j] = xr0[lane + 32 * j]; v1[j] = xr1[lane + 32 * j]; }
        float a0 = 0.f, a1 = 0.f;
#pragma unroll
        for (int j = 0; j < 8; j++) {
            a0 += v0[j].x * v0[j].x + v0[j].y * v0[j].y + v0[j].z * v0[j].z + v0[j].w * v0[j].w;
            a1 += v1[j].x * v1[j].x + v1[j].y * v1[j].y + v1[j].z * v1[j].z + v1[j].w * v1[j].w;
            uchar4 q0, q1;
            q0.x = to_e4m3(v0[j].x); q0.y = to_e4m3(v0[j].y);
            q0.z = to_e4m3(v0[j].z); q0.w = to_e4m3(v0[j].w);
            q1.x = to_e4m3(v1[j].x); q1.y = to_e4m3(v1[j].y);
            q1.z = to_e4m3(v1[j].z); q1.w = to_e4m3(v1[j].w);
            dst0[lane + 32 * j] = q0;
            dst1[lane + 32 * j] = q1;
        }
#pragma unroll
        for (int o = 16; o > 0; o >>= 1) {
            a0 += __shfl_xor_sync(0xFFFFFFFFu, a0, o);
            a1 += __shfl_xor_sync(0xFFFFFFFFu, a1, o);
        }
        if (lane == 0) { g_x_sq[row0] = a0; g_x_sq[row0 + 1] = a1; }
    } else {
        __shared__ float tile[128][33];     // tile[k_local][n_local], padded
        __shared__ float partial[8][33];
        const int b2 = blockIdx.x - CONV_BLOCKS;
        const int n0 = (b2 % TR_NBLK) * 32;
        const int k_blk = b2 / TR_NBLK;     // 0..7
        const int k0 = k_blk * 128;
        const int lane = tid & 31, w = tid >> 5;   // 8 warps

        // load: warp per k-row, 32 contiguous floats (128B) per row
#pragma unroll
        for (int kk = 0; kk < 128; kk += 8)
            tile[kk + w][lane] = p[(size_t)(k0 + kk + w) * OUTDIM + n0 + lane];
        __syncthreads();

        // store: thread (n_local=lane, kc=w) quantizes 16 consecutive k, one 16B store
        {
            union { uint4 u; uint8_t b[16]; } pk;
            float sq = 0.f;
#pragma unroll
            for (int j = 0; j < 16; j++) {
                float v = tile[w * 16 + j][lane];
                sq += v * v;
                pk.b[j] = to_e4m3(32.0f * v);
            }
            *reinterpret_cast<uint4*>(g_pt_fp8 + (size_t)(n0 + lane) * INDIM + k0 + w * 16) = pk.u;
            partial[w][lane] = sq;
        }
        __syncthreads();
        if (w == 0) {
            float s = 0.f;
#pragma unroll
            for (int j = 0; j < 8; j++) s += partial[j][lane];
            g_psq_part[k_blk][n0 + lane] = s;
        }
    }
}

// ---------------- stage loader (256 threads) — R7/R14 verbatim ----------------
__device__ __forceinline__ void load_stage(uint32_t smem_base, int buf, int m0, int n0,
                                           int k0, int tid) {
    uint32_t a_s = smem_base + SMEM_TILES_OFF + (uint32_t)buf * STAGE_BYTES;
    uint32_t b_s = a_s + BM * 128u;
    const uint8_t* abase = g_x_fp8 + (size_t)m0 * INDIM + k0;
#pragma unroll
    for (int i = 0; i < (BM * 8) / GEMM_THREADS; i++) {   // 4 chunks/thread
        int idx = tid + i * GEMM_THREADS;
        int r = idx >> 3, c = idx & 7;
        cp_async16(a_s + sw128((uint32_t)(r * 128 + c * 16)),
                   abase + (size_t)r * INDIM + c * 16);
    }
    const uint8_t* bbase = g_pt_fp8 + (size_t)n0 * INDIM + k0;
#pragma unroll
    for (int i = 0; i < (BN * 8) / GEMM_THREADS; i++) {   // 4 chunks/thread
        int idx = tid + i * GEMM_THREADS;
        int r = idx >> 3, c = idx & 7;
        cp_async16(b_s + sw128((uint32_t)(r * 128 + c * 16)),
                   bbase + (size_t)r * INDIM + c * 16);
    }
}

// ---------------- GEMM: R14 champion config (92.8us measured) ----------------
__global__ void __launch_bounds__(GEMM_THREADS, 2)
gemm_kernel(float* __restrict__ out) {
    extern __shared__ char smem[];
    uint32_t smem_base = smem_to_u32(smem);
    const int tid = threadIdx.x;
    const int wid = tid >> 5;
    const int lid = tid & 31;
    const int wm = wid & 3;         // 4 warps along M (32 rows each)
    const int wn = wid >> 2;        // 2 warps along N (64 cols each)
    const int n0 = blockIdx.x * BN;
    const int m0 = blockIdx.y * BM;

    // prologue loads first so the psq reduction below overlaps the cp.async latency
#pragma unroll
    for (int s = 0; s < STAGES - 1; s++) {
        load_stage(smem_base, s, m0, n0, s * BK, tid);
        CP_COMMIT();
    }

    // reduce psq partials into smem tile: psq[n] = sum_k g_psq_part[k][n]
    for (int i = tid; i < BN; i += GEMM_THREADS) {
        float s0 = 0.f, s1 = 0.f, s2 = 0.f, s3 = 0.f;
#pragma unroll
        for (int j = 0; j < TR_KBLK; j += 4) {
            s0 += g_psq_part[j + 0][n0 + i];
            s1 += g_psq_part[j + 1][n0 + i];
            s2 += g_psq_part[j + 2][n0 + i];
            s3 += g_psq_part[j + 3][n0 + i];
        }
        *reinterpret_cast<float*>(smem + SMEM_PSQ_OFF + i * 4) = (s0 + s1) + (s2 + s3);
    }

    uint32_t acc[2][8][2];          // fp16x2 accumulators
#pragma unroll
    for (int mi = 0; mi < 2; mi++)
#pragma unroll
        for (int nt = 0; nt < 8; nt++) {
            acc[mi][nt][0] = 0u; acc[mi][nt][1] = 0u;
        }

    // per-lane ldmatrix row/offset components
    const int a_row = wm * 32 + (lid & 15);                   // + mi*16
    const int a_kb  = (lid >> 4) * 16;
    const int sub   = lid >> 3;
    const int b_row = wn * 64 + (sub >> 1) * 8 + (lid & 7);   // + nj*16
    const int b_kb  = (sub & 1) * 16;

    int buf = 0;
    int pbuf = STAGES - 1;          // buffer to prefetch into
    for (int s = 0; s < NSTAGE_K; s++) {
        CP_WAIT(STAGES - 2);                   // stage s landed (this thread)
        __syncthreads();                       // landed for all; all finished compute(s-1)
        if (s + STAGES - 1 < NSTAGE_K)
            load_stage(smem_base, pbuf, m0, n0, (s + STAGES - 1) * BK, tid);
        CP_COMMIT();                           // empty group when no loads

        const uint32_t t_s = smem_base + SMEM_TILES_OFF + (uint32_t)buf * STAGE_BYTES;
        const uint32_t a_s = t_s;
        const uint32_t b_s = t_s + BM * 128u;

#pragma unroll
        for (int ks = 0; ks < 4; ks++) {       // 4 k-chunks of 32 bytes
            const int k0b = ks * 32;
            uint32_t afrag[2][4];
#pragma unroll
            for (int mi = 0; mi < 2; mi++) {
                uint32_t off = (uint32_t)((a_row + mi * 16) * 128 + k0b + a_kb);
                ldmatrix_x4(afrag[mi], a_s + sw128(off));
            }
            uint32_t bfrag[8][2];
#pragma unroll
            for (int nj = 0; nj < 4; nj++) {
                uint32_t off = (uint32_t)((b_row + nj * 16) * 128 + k0b + b_kb);
                uint32_t t[4];
                ldmatrix_x4(t, b_s + sw128(off));
                bfrag[nj * 2][0] = t[0]; bfrag[nj * 2][1] = t[1];
                bfrag[nj * 2 + 1][0] = t[2]; bfrag[nj * 2 + 1][1] = t[3];
            }
#pragma unroll
            for (int mi = 0; mi < 2; mi++)
#pragma unroll
                for (int nt = 0; nt < 8; nt++)
                    mma_fp8_h(acc[mi][nt], afrag[mi], bfrag[nt]);
        }
        buf = (buf + 1 == STAGES) ? 0 : buf + 1;
        pbuf = (pbuf + 1 == STAGES) ? 0 : pbuf + 1;
    }

    // fused epilogue: out = (2/32)*acc - x_sq[m] - p_sq[n]
    const float* psq_s = reinterpret_cast<const float*>(smem + SMEM_PSQ_OFF);
    const int lane4 = lid >> 2;
    const int lane2 = (lid & 3) * 2;
#pragma unroll
    for (int mi = 0; mi < 2; mi++) {
#pragma unroll
        for (int h = 0; h < 2; h++) {
            const int r = m0 + wm * 32 + mi * 16 + lane4 + h * 8;
            const float xs = g_x_sq[r];
            float* orow = out + (size_t)r * OUTDIM + n0 + wn * 64;
#pragma unroll
            for (int nt = 0; nt < 8; nt++) {
                const int cn = nt * 8 + lane2;
                __half2 hv = *reinterpret_cast<const __half2*>(&acc[mi][nt][h]);
                float2 w;
                w.x = fmaf(ACC_SCALE, __half2float(__low2half(hv)),
                           -xs - psq_s[wn * 64 + cn]);
                w.y = fmaf(ACC_SCALE, __half2float(__high2half(hv)),
                           -xs - psq_s[wn * 64 + cn + 1]);
                *reinterpret_cast<float2*>(orow + cn) = w;
            }
        }
    }
}

// ---------------- launch ----------------
extern "C" void kernel_launch(void* const* d_in, const int* in_sizes, int n_in,
                              void* d_out, int out_size) {
    const float* x = (const float*)d_in[0];
    const float* p = (const float*)d_in[1];
    if (n_in >= 2 && in_sizes[0] == OUTDIM * INDIM && in_sizes[1] == BATCH * INDIM) {
        x = (const float*)d_in[1];
        p = (const float*)d_in[0];
    }
    float* out = (float*)d_out;

    prep_kernel<<<PREP_BLOCKS, 256>>>(x, p);

    cudaFuncSetAttribute(gemm_kernel, cudaFuncAttributeMaxDynamicSharedMemorySize,
                         SMEM_TOTAL);
    gemm_kernel<<<dim3(OUTDIM / BN, BATCH / BM), GEMM_THREADS, SMEM_TOTAL>>>(out);
}